// round 7
// baseline (speedup 1.0000x reference)
#include <cuda_runtime.h>
#include <cuda_device_runtime_api.h>

// Derivation: layer_norm over the size-1 kv feature axis returns exactly
// ln_k_b (mu=x, var=0), so k and v are identical for every key position;
// softmax over identical scores is uniform; o = mean_l(v) = v for every query.
// Hence out = msa + row, row[c] = sum_d (ln_k_b*Wv[d] + bv[d])*Wo[d,c] + bo[c],
// broadcast over all 16384 rows. Exact identity, independent of input values.
__device__ float g_row[256];

// Kernel 1 (PDL primary): 64 blocks x 256 threads; block b -> row[4b..4b+4).
__global__ void compute_row_kernel(const float* __restrict__ ln_k_b,
                                   const float* __restrict__ Wv,   // [1,256]
                                   const float* __restrict__ bv,   // [256]
                                   const float* __restrict__ Wo,   // [256,256]
                                   const float* __restrict__ bo)   // [256]
{
    __shared__ float4 part[256];
    int t = threadIdx.x;
    int c4 = blockIdx.x;               // channels 4*c4 .. 4*c4+3
    float kb = ln_k_b[0];
    float vd = fmaf(kb, Wv[t], bv[t]); // v[d=t]; kv_x == ln_k_b exactly

    float4 w = reinterpret_cast<const float4*>(Wo)[t * 64 + c4];
    float4 p;
    p.x = vd * w.x; p.y = vd * w.y; p.z = vd * w.z; p.w = vd * w.w;
    part[t] = p;
    __syncthreads();

    #pragma unroll
    for (int s = 128; s >= 1; s >>= 1) {
        if (t < s) {
            float4 a = part[t], b = part[t + s];
            a.x += b.x; a.y += b.y; a.z += b.z; a.w += b.w;
            part[t] = a;
        }
        __syncthreads();
    }
    if (t == 0) {
        float4 r = part[0];
        float4 b4 = reinterpret_cast<const float4*>(bo)[c4];
        r.x += b4.x; r.y += b4.y; r.z += b4.z; r.w += b4.w;
        reinterpret_cast<float4*>(g_row)[c4] = r;
    }
    // signal PDL completion as early as possible (all results are written)
    cudaTriggerProgrammaticLaunchCompletion();
}

// Kernel 2 (PDL secondary): out = msa + broadcast(row).
// 1024 blocks x 256 threads x 4 float4/thread = 1,048,576 float4 exactly.
// All 4 independent loads are issued BEFORE the grid-dependency sync, so
// kernel 1 and the launch gap hide under the load ramp.
__global__ void __launch_bounds__(256)
add_row_kernel(const float4* __restrict__ msa4,
               float4* __restrict__ out4)
{
    const int t = threadIdx.x;
    const int base = blockIdx.x * (256 * 4) + t;

    float4 m0 = msa4[base];
    float4 m1 = msa4[base + 256];
    float4 m2 = msa4[base + 512];
    float4 m3 = msa4[base + 768];

    // wait for compute_row_kernel's writes to be visible
    cudaGridDependencySynchronize();
    asm volatile("" ::: "memory");

    // (element index) mod 64 == t mod 64 for all 4 elements (stride 256)
    const float4 r = reinterpret_cast<const float4*>(g_row)[t & 63];

    m0.x += r.x; m0.y += r.y; m0.z += r.z; m0.w += r.w;
    m1.x += r.x; m1.y += r.y; m1.z += r.z; m1.w += r.w;
    m2.x += r.x; m2.y += r.y; m2.z += r.z; m2.w += r.w;
    m3.x += r.x; m3.y += r.y; m3.z += r.z; m3.w += r.w;

    out4[base]       = m0;
    out4[base + 256] = m1;
    out4[base + 512] = m2;
    out4[base + 768] = m3;
}

// Shape-general fallback (only used if out_size isn't 1024*1024 float4).
__global__ void add_row_fallback(const float4* __restrict__ msa4,
                                 float4* __restrict__ out4, int n4)
{
    int i = blockIdx.x * blockDim.x + threadIdx.x;
    if (i < n4) {
        float4 m = msa4[i];
        float4 r = reinterpret_cast<const float4*>(g_row)[i & 63];
        m.x += r.x; m.y += r.y; m.z += r.z; m.w += r.w;
        out4[i] = m;
    }
}

extern "C" void kernel_launch(void* const* d_in, const int* in_sizes, int n_in,
                              void* d_out, int out_size)
{
    // metadata order: 0 msa, 1 saxs, 2 ln_q_w, 3 ln_q_b, 4 ln_k_w, 5 ln_k_b,
    //                 6 Wq, 7 bq, 8 Wk, 9 bk, 10 Wv, 11 bv, 12 Wo, 13 bo
    const float* msa    = (const float*)d_in[0];
    const float* ln_k_b = (const float*)d_in[5];
    const float* Wv     = (const float*)d_in[10];
    const float* bv     = (const float*)d_in[11];
    const float* Wo     = (const float*)d_in[12];
    const float* bo     = (const float*)d_in[13];
    float* out = (float*)d_out;

    compute_row_kernel<<<64, 256>>>(ln_k_b, Wv, bv, Wo, bo);

    int n4 = out_size / 4;
    if (n4 == 1024 * 1024) {
        cudaLaunchConfig_t cfg = {};
        cfg.gridDim  = dim3(1024, 1, 1);
        cfg.blockDim = dim3(256, 1, 1);
        cfg.dynamicSmemBytes = 0;
        cfg.stream = 0;  // capturing (legacy default) stream
        cudaLaunchAttribute attr[1];
        attr[0].id = cudaLaunchAttributeProgrammaticStreamSerialization;
        attr[0].val.programmaticStreamSerializationAllowed = 1;
        cfg.attrs = attr;
        cfg.numAttrs = 1;
        cudaError_t e = cudaLaunchKernelEx(&cfg, add_row_kernel,
                                           (const float4*)msa, (float4*)out);
        if (e != cudaSuccess) {
            // plain serialized launch as a safety net
            add_row_kernel<<<1024, 256>>>((const float4*)msa, (float4*)out);
        }
    } else {
        add_row_fallback<<<(n4 + 255) / 256, 256>>>(
            (const float4*)msa, (float4*)out, n4);
    }
}